// round 17
// baseline (speedup 1.0000x reference)
#include <cuda_runtime.h>
#include <cuda_bf16.h>
#include <cstdint>

// Problem constants (fixed shapes)
#define H     200
#define D     128
#define NT    256
#define ASD   136        // row stride (bf16) for A and Wk tiles (+8 pad)
#define WK_BYTES (128*ASD*2)     // 34816
#define CH_WK (WK_BYTES/16)      // 2176

// mainAB smem layout (split kernel: 112 rows of A max)
#define A_OFF   0
#define A_SZ    (112*ASD*2)              // 30464
#define W_OFF   (A_OFF + A_SZ)           // 30464
#define SW_OFF  (W_OFF + WK_BYTES)       // 65280   [8][200] f32
#define Q_OFF   (SW_OFF + 8*H*4)         // 71680
#define SMEM_A_BYTES (Q_OFF + 512)       // 72192 -> 3 CTAs/SM

__device__ __align__(16) float          g_geo[1024];
__device__ __align__(16) __nv_bfloat16  g_Wkb[128 * ASD];    // Wk bf16, padded
__device__ __align__(16) float          g_q[1024 * D];       // pre-scaled
__device__ __align__(16) float          g_tv[1024 * D];
__device__ __align__(16) float          g_tgt[1024 * D];
__device__ __align__(16) float          g_dv[1024 * H];      // hist_i . tv
__device__ __align__(16) float          g_dt[1024 * H];      // hist_i . tgt
__device__ __align__(16) float          g_swp[2048 * H];     // per-half scores

// ---------------------------------------------------------------------------
__device__ __forceinline__ void cp16(uint32_t dst, const void* src) {
    asm volatile("cp.async.cg.shared.global [%0], [%1], 16;\n"
                 :: "r"(dst), "l"(src));
}
__device__ __forceinline__ void ldsm4(unsigned& r0, unsigned& r1, unsigned& r2,
                                      unsigned& r3, uint32_t addr) {
    asm volatile("ldmatrix.sync.aligned.m8n8.x4.shared.b16 {%0,%1,%2,%3}, [%4];\n"
                 : "=r"(r0), "=r"(r1), "=r"(r2), "=r"(r3) : "r"(addr));
}
__device__ __forceinline__ void mma16816(float* c, unsigned a0, unsigned a1,
                                         unsigned a2, unsigned a3,
                                         unsigned b0, unsigned b1) {
    asm volatile("mma.sync.aligned.m16n8k16.row.col.f32.bf16.bf16.f32 "
                 "{%0,%1,%2,%3}, {%4,%5,%6,%7}, {%8,%9}, {%0,%1,%2,%3};\n"
                 : "+f"(c[0]), "+f"(c[1]), "+f"(c[2]), "+f"(c[3])
                 : "r"(a0), "r"(a1), "r"(a2), "r"(a3), "r"(b0), "r"(b1));
}
__device__ __forceinline__ unsigned bf2_as_u32(__nv_bfloat162 v) {
    unsigned u;
    memcpy(&u, &v, 4);
    return u;
}

// ---------------------------------------------------------------------------
// Prep 1 (fused): blocks 0-255 qtv | 256-287 Wk->bf16 | 288-487 geo.
// ---------------------------------------------------------------------------
__global__ __launch_bounds__(NT)
void prep1_kernel(const int* __restrict__ target, const int* __restrict__ tregion,
                  const float* __restrict__ embT, const float* __restrict__ embR,
                  const float* __restrict__ Wq, const float* __restrict__ Wv,
                  const float* __restrict__ Wk,
                  const int* __restrict__ hregion, const float* __restrict__ embD,
                  const int* __restrict__ uidp, int b, int region_num) {
    __shared__ float tgt4[4][D];
    __shared__ float red[8];
    const int blk = blockIdx.x;
    const int tid = threadIdx.x, wid = tid >> 5, lane = tid & 31;

    if (blk < 256) {
        const int b0 = blk * 4;
        for (int i = tid; i < 4 * D; i += NT) {
            int j = i >> 7, e = i & 127, bb = b0 + j;
            int ti = target[bb], tr = tregion[bb];
            float v = (e < 64) ? embT[(size_t)ti * 64 + e]
                               : embR[(size_t)tr * 64 + (e - 64)];
            tgt4[j][e] = v;
            g_tgt[(size_t)bb * D + e] = v;
        }
        __syncthreads();

        if (wid < 4) {
            float4 tg[4];
#pragma unroll
            for (int j = 0; j < 4; j++) tg[j] = *(const float4*)&tgt4[j][lane * 4];
            for (int cb = 0; cb < 32; cb += 8) {
                float4 wv[8];
#pragma unroll
                for (int jj = 0; jj < 8; jj++)
                    wv[jj] = *(const float4*)(Wq + (wid * 32 + cb + jj) * D + lane * 4);
#pragma unroll
                for (int j = 0; j < 4; j++) {
                    float p[8];
#pragma unroll
                    for (int jj = 0; jj < 8; jj++)
                        p[jj] = wv[jj].x * tg[j].x + wv[jj].y * tg[j].y +
                                wv[jj].z * tg[j].z + wv[jj].w * tg[j].w;
#pragma unroll
                    for (int o = 16; o; o >>= 1)
#pragma unroll
                        for (int jj = 0; jj < 8; jj++)
                            p[jj] += __shfl_xor_sync(0xffffffffu, p[jj], o);
                    if (lane == 0) {
#pragma unroll
                        for (int jj = 0; jj < 8; jj++)
                            g_q[(size_t)(b0 + j) * D + wid * 32 + cb + jj] =
                                p[jj] * 0.088388347648318447f;
                    }
                }
            }
        } else {
            int e = tid - 128;
            float acc0 = 0.f, acc1 = 0.f, acc2 = 0.f, acc3 = 0.f;
#pragma unroll 16
            for (int c = 0; c < D; c++) {
                float w = Wv[c * D + e];
                acc0 += tgt4[0][c] * w;
                acc1 += tgt4[1][c] * w;
                acc2 += tgt4[2][c] * w;
                acc3 += tgt4[3][c] * w;
            }
            g_tv[(size_t)(b0 + 0) * D + e] = acc0;
            g_tv[(size_t)(b0 + 1) * D + e] = acc1;
            g_tv[(size_t)(b0 + 2) * D + e] = acc2;
            g_tv[(size_t)(b0 + 3) * D + e] = acc3;
        }
    } else if (blk < 288) {
        int i2 = (blk - 256) * 256 + tid;
        if (i2 < 8192) {
            int c = i2 >> 6, e2 = (i2 & 63) << 1;
            float2 v = *(const float2*)(Wk + c * D + e2);
            *(__nv_bfloat162*)&g_Wkb[c * ASD + e2] =
                __floats2bfloat162_rn(v.x, v.y);
        }
    } else {
        const float* erow = embD + (size_t)uidp[0] * (size_t)region_num;
        int j = blk - 288;
        float s = 0.f;
        for (int bb = tid; bb < b; bb += NT)
            s += erow[tregion[bb]] * erow[hregion[bb * H + j]];
#pragma unroll
        for (int o = 16; o; o >>= 1) s += __shfl_down_sync(0xffffffffu, s, o);
        if (lane == 0) red[wid] = s;
        __syncthreads();
        if (tid == 0) {
            float t = 0.f;
#pragma unroll
            for (int i = 0; i < 8; i++) t += red[i];
            g_geo[j] = -1.0f / (fmaxf(t, 0.f) + 1.0f);
        }
    }
}

// ---------------------------------------------------------------------------
// Main AB: 2 CTAs per batch (half = m-tile range), 3 CTAs/SM.
// In-kernel gather (embT/embR -> smem bf16, + dv/dt bilinears) overlapped
// with cp.async Wk/q fill -> MMA GEMM with fused reshape-score epilogue.
// ---------------------------------------------------------------------------
__global__ __launch_bounds__(NT, 3)
void mainAB_kernel(const int* __restrict__ history, const int* __restrict__ hregion,
                   const float* __restrict__ embT, const float* __restrict__ embR) {
    extern __shared__ char smem[];
    __nv_bfloat16* As  = (__nv_bfloat16*)(smem + A_OFF);    // [<=112][136]
    __nv_bfloat16* Wkb = (__nv_bfloat16*)(smem + W_OFF);    // [128][136]
    float* sw  = (float*)(smem + SW_OFF);                   // [8][200]
    float* q_s = (float*)(smem + Q_OFF);

    const int bid  = blockIdx.x;
    const int b    = bid >> 1;
    const int half = bid & 1;
    const int row0 = half * 112;
    const int Rpad = half ? 96 : 112;     // rows incl pad (tiles of 16)
    const int T    = half ? 6 : 7;        // m-tiles
    const int tid  = threadIdx.x;
    const int wid  = tid >> 5, lane = tid & 31;

    // ---- phase A1: issue async fills (Wk tile + q vector) ----------------
    {
        uint32_t wk_u = (uint32_t)__cvta_generic_to_shared(Wkb);
        const char* wk = (const char*)g_Wkb;
        for (int i = tid; i < CH_WK; i += NT) cp16(wk_u + i * 16, wk + i * 16);
        if (tid < 32) {
            uint32_t u = (uint32_t)__cvta_generic_to_shared(q_s);
            cp16(u + tid * 16, (const char*)(g_q + (size_t)b * D) + tid * 16);
        }
        asm volatile("cp.async.commit_group;\n" ::: "memory");
    }
    for (int i = tid; i < 8 * H; i += NT) sw[i] = 0.f;      // zero partials

    // ---- phase A2: direct gather into smem + dv/dt (overlaps cp.async) ---
    {
        const int e4 = lane * 4;
        const float4 tvv = *(const float4*)(g_tv + (size_t)b * D + e4);
        const float4 tgg = *(const float4*)(g_tgt + (size_t)b * D + e4);
#pragma unroll 2
        for (int lr = wid; lr < Rpad; lr += 8) {
            int rg = row0 + lr;
            if (rg < H) {
                int hi = __ldg(history + b * H + rg);
                int hg = __ldg(hregion + b * H + rg);
                const float* src = (lane < 16)
                    ? (embT + (size_t)hi * 64 + e4)
                    : (embR + (size_t)hg * 64 + (e4 - 64));
                float4 v = *(const float4*)src;
                uint2 pk;
                pk.x = bf2_as_u32(__floats2bfloat162_rn(v.x, v.y));
                pk.y = bf2_as_u32(__floats2bfloat162_rn(v.z, v.w));
                *(uint2*)&As[lr * ASD + e4] = pk;
                float pdv = v.x * tvv.x + v.y * tvv.y + v.z * tvv.z + v.w * tvv.w;
                float pdt = v.x * tgg.x + v.y * tgg.y + v.z * tgg.z + v.w * tgg.w;
#pragma unroll
                for (int o = 16; o; o >>= 1) {
                    pdv += __shfl_xor_sync(0xffffffffu, pdv, o);
                    pdt += __shfl_xor_sync(0xffffffffu, pdt, o);
                }
                if (lane == 0) {
                    g_dv[(size_t)b * H + rg] = pdv;
                    g_dt[(size_t)b * H + rg] = pdt;
                }
            } else {
                uint2 z = {0u, 0u};
                *(uint2*)&As[lr * ASD + e4] = z;
            }
        }
    }
    asm volatile("cp.async.wait_group 0;\n" ::: "memory");
    __syncthreads();

    // ---- phase B: GEMM + fused score epilogue ---------------------------
    {
        uint32_t as_base = (uint32_t)__cvta_generic_to_shared(As);
        uint32_t wk_base = (uint32_t)__cvta_generic_to_shared(Wkb);
        float* swp = sw + wid * H;
        for (int u = wid; u < 2 * T; u += 8) {
            int m0 = (u >> 1) * 16;                     // local row base
            int nb = (u & 1) * 64;
            float c[8][4];
#pragma unroll
            for (int i = 0; i < 8; i++)
#pragma unroll
                for (int j = 0; j < 4; j++) c[i][j] = 0.f;

            uint32_t a_addr0 = as_base +
                ((m0 + (lane & 15)) * ASD + ((lane >> 4) << 3)) * 2;
#pragma unroll
            for (int ks = 0; ks < 8; ks++) {
                int k0 = ks * 16;
                unsigned a0, a1, a2, a3;
                ldsm4(a0, a1, a2, a3, a_addr0 + k0 * 2);
#pragma unroll
                for (int p = 0; p < 4; p++) {
                    int n0 = nb + p * 16;
                    uint32_t b_addr = wk_base +
                        ((n0 + (lane & 7) + ((lane >> 4) << 3)) * ASD +
                         k0 + (((lane >> 3) & 1) << 3)) * 2;
                    unsigned b0, b1, b2, b3;
                    ldsm4(b0, b1, b2, b3, b_addr);
                    mma16816(c[2 * p],     a0, a1, a2, a3, b0, b1);
                    mma16816(c[2 * p + 1], a0, a1, a2, a3, b2, b3);
                }
            }
            // fused epilogue (per-instruction lane sets never collide mod 200)
            int lrow0 = m0 + (lane >> 2);
            int colb = (lane & 3) << 1;
#pragma unroll
            for (int p = 0; p < 4; p++) {
#pragma unroll
                for (int q = 0; q < 2; q++) {
                    float* cc = c[2 * p + q];
                    int col = nb + p * 16 + q * 8 + colb;
#pragma unroll
                    for (int hh = 0; hh < 2; hh++) {
                        int rg = row0 + lrow0 + hh * 8;  // global row
                        if (rg < H) {
                            int j0 = rg * 128 + col;
                            swp[j0 % H]       += q_s[j0 / H]       * cc[2 * hh];
                            swp[(j0 + 1) % H] += q_s[(j0 + 1) / H] * cc[2 * hh + 1];
                        }
                    }
                }
            }
        }
    }
    __syncthreads();

    // ---- phase C: fold 8 warp partials, store slice ---------------------
    if (tid < H) {
        float s = 0.f;
#pragma unroll
        for (int w = 0; w < 8; w++) s += sw[w * H + tid];
        g_swp[(size_t)bid * H + tid] = s;
    }
}

// ---------------------------------------------------------------------------
__device__ __forceinline__ float block_sum(float v, float* red) {
    int lane = threadIdx.x & 31, w = threadIdx.x >> 5;
#pragma unroll
    for (int o = 16; o; o >>= 1) v += __shfl_down_sync(0xffffffffu, v, o);
    __syncthreads();
    if (lane == 0) red[w] = v;
    __syncthreads();
    float s = (threadIdx.x < 8) ? red[threadIdx.x] : 0.f;
    if (w == 0) {
#pragma unroll
        for (int o = 4; o; o >>= 1) s += __shfl_down_sync(0xffffffffu, s, o);
        if (lane == 0) red[0] = s;
    }
    __syncthreads();
    return red[0];
}

// ---------------------------------------------------------------------------
// Finalize: one CTA per batch. exp/attn/geo + bilinear reduction + sigmoid.
// ---------------------------------------------------------------------------
__global__ __launch_bounds__(NT)
void finalize_kernel(const int* __restrict__ history, const int* __restrict__ target,
                     const float* __restrict__ hv, const float* __restrict__ dist,
                     float* __restrict__ out) {
    __shared__ float red[8];
    const int b = blockIdx.x, tid = threadIdx.x;
    const int tgt_i = target[b];

    float me = 0.f;
    if (tid < H) {
        float sc = g_swp[(size_t)(2 * b) * H + tid] +
                   g_swp[(size_t)(2 * b + 1) * H + tid];
        me = (history[b * H + tid] != tgt_i) ? __expf(sc) : 0.f;
    }
    float S = block_sum(me, red);

    float contrib = 0.f;
    if (tid < H) {
        float attn = me / sqrtf(S);                      // exp_sum ** 0.5
        float geo  = __expf(g_geo[tid] * dist[b * H + tid]);
        contrib = (attn + geo) * g_dv[(size_t)b * H + tid] +
                  hv[tid] * g_dt[(size_t)b * H + tid];
    }
    float pred = block_sum(contrib, red);
    if (tid == 0) out[b] = 1.0f / (1.0f + __expf(-pred));
}

// ---------------------------------------------------------------------------
extern "C" void kernel_launch(void* const* d_in, const int* in_sizes, int n_in,
                              void* d_out, int out_size) {
    const int*   history = (const int*)  d_in[0];
    const int*   target  = (const int*)  d_in[1];
    const int*   hregion = (const int*)  d_in[2];
    const int*   tregion = (const int*)  d_in[3];
    const float* hv      = (const float*)d_in[4];
    const float* dist    = (const float*)d_in[5];
    const int*   uid     = (const int*)  d_in[6];
    const float* embT    = (const float*)d_in[7];
    const float* embR    = (const float*)d_in[8];
    const float* embD    = (const float*)d_in[9];
    const float* Wq      = (const float*)d_in[10];
    const float* Wk      = (const float*)d_in[11];
    const float* Wv      = (const float*)d_in[12];
    float*       out     = (float*)d_out;

    int b          = in_sizes[1];          // 1024
    int region_num = in_sizes[8] / 64;     // 1000

    cudaFuncSetAttribute(mainAB_kernel, cudaFuncAttributeMaxDynamicSharedMemorySize,
                         SMEM_A_BYTES);

    prep1_kernel<<<488, NT>>>(target, tregion, embT, embR, Wq, Wv, Wk,
                              hregion, embD, uid, b, region_num);
    mainAB_kernel<<<2 * b, NT, SMEM_A_BYTES>>>(history, hregion, embT, embR);
    finalize_kernel<<<b, NT>>>(history, target, hv, dist, out);
}